// round 12
// baseline (speedup 1.0000x reference)
#include <cuda_runtime.h>
#include <cuda_fp16.h>
#include <cstdint>

// Problem constants
#define E_TOTAL   640000
#define N_NODES   20000
#define N_GRAPHS  16
#define TILE_M    256
#define NTHREADS  512

// half2 strides (in half2 units)
#define LDA  68   // X [256][64 h2], W1 [128][64 h2], H [256][64 h2], W2T [64][64 h2]

// smem byte offsets
#define SMEM_X    0        // 256*68*4 = 69632
#define SMEM_W1   69632    // 128*68*4 = 34816 -> 104448
#define SMEM_H    0        // 69632 (aliases X only; W1 untouched by H)
#define SMEM_W2T  104448   // 64*68*4 = 17408 -> 121856
#define OFF_S     121856
#define OFF_R     122880
#define OFF_G     123904
#define OFF_MSK   124928
#define OFF_B1    125952
#define OFF_B2    126464
#define SMEM_BYTES 126720

// ---------- scratch (fp16 pre-converted) ----------
__device__ __half2 g_mn2[N_NODES * 32];    // masked nodes [node][32 h2]
__device__ __half2 g_w1t2[128 * 128];      // W1^T [n=128][k2=128]
__device__ __half2 g_w2t2[64 * 64];        // W2^T [n=64][k2=64]
__device__ __half2 g_ga2[N_GRAPHS * 32];   // global_attr fp16 [g][32 h2]
__device__ int     g_is64;

__device__ __forceinline__ void mma_f16(float c[4], const uint32_t a[4], const uint32_t b[2]) {
    asm volatile(
        "mma.sync.aligned.m16n8k16.row.col.f32.f16.f16.f32 "
        "{%0,%1,%2,%3}, {%4,%5,%6,%7}, {%8,%9}, {%0,%1,%2,%3};"
        : "+f"(c[0]), "+f"(c[1]), "+f"(c[2]), "+f"(c[3])
        : "r"(a[0]), "r"(a[1]), "r"(a[2]), "r"(a[3]), "r"(b[0]), "r"(b[1]));
}
__device__ __forceinline__ uint32_t h2u(__half2 h) { return *(uint32_t*)&h; }

// ---------- single prep kernel ----------
// blocks [0,2500): masked nodes; [2500,2564): W1^T; [2564,2580): W2^T;
// [2580,2582): global_attr fp16; 2582: index dtype detect.
#define PREP_BLOCKS 2583
__global__ void prep_all(const float* __restrict__ na, const float* __restrict__ nm,
                         const float* __restrict__ W1, const float* __restrict__ W2,
                         const float* __restrict__ ga, const int* __restrict__ ei_words) {
    int bid = blockIdx.x, tid = threadIdx.x;
    if (bid < 2500) {
        int i = bid * 256 + tid;
        if (i < N_NODES * 32) {
            int node = i >> 5, c2 = i & 31;
            float m = nm[node];
            const float* s = na + (size_t)node * 64 + c2 * 2;
            g_mn2[i] = __floats2half2_rn(s[0] * m, s[1] * m);
        }
    } else if (bid < 2564) {
        int j = (bid - 2500) * 256 + tid;       // < 16384
        int n = j >> 7, k2 = j & 127;
        g_w1t2[j] = __floats2half2_rn(W1[(2 * k2) * 128 + n], W1[(2 * k2 + 1) * 128 + n]);
    } else if (bid < 2580) {
        int j = (bid - 2564) * 256 + tid;       // < 4096
        int n = j >> 6, k2 = j & 63;
        g_w2t2[j] = __floats2half2_rn(W2[(2 * k2) * 64 + n], W2[(2 * k2 + 1) * 64 + n]);
    } else if (bid < 2582) {
        int j = (bid - 2580) * 256 + tid;       // < 512
        if (j < N_GRAPHS * 32) {
            int gi = j >> 5, c2 = j & 31;
            g_ga2[j] = __floats2half2_rn(ga[gi * 64 + 2 * c2], ga[gi * 64 + 2 * c2 + 1]);
        }
    } else {
        __shared__ int nz;
        if (tid == 0) nz = 0;
        __syncthreads();
        int w = ei_words[2 * tid * 2500 + 1];
        if (w != 0) atomicAdd(&nz, 1);
        __syncthreads();
        if (tid == 0) g_is64 = (nz == 0) ? 1 : 0;
    }
}

// ---------- fused edge MLP: 256-edge tiles, 32x64 warp tiles, occ 1 ----------
__global__ __launch_bounds__(NTHREADS, 1)
void edge_mlp_kernel(const float* __restrict__ edge_attr,
                     const float* __restrict__ edge_mask,
                     const void* __restrict__ edge_index,
                     const void* __restrict__ eg_index,
                     const float* __restrict__ b1,
                     const float* __restrict__ b2,
                     float* __restrict__ out) {
    extern __shared__ char smp[];
    __half2* sX2  = (__half2*)(smp + SMEM_X);
    __half2* sW12 = (__half2*)(smp + SMEM_W1);
    __half2* sH2  = (__half2*)(smp + SMEM_H);
    __half2* sW22 = (__half2*)(smp + SMEM_W2T);
    int*   sS   = (int*)(smp + OFF_S);
    int*   sR   = (int*)(smp + OFF_R);
    int*   sG   = (int*)(smp + OFF_G);
    float* sMsk = (float*)(smp + OFF_MSK);
    float* sB1  = (float*)(smp + OFF_B1);
    float* sB2  = (float*)(smp + OFF_B2);

    const int tid  = threadIdx.x;
    const int lane = tid & 31;
    const int w    = tid >> 5;           // 0..15
    const int g    = lane >> 2;
    const int t    = lane & 3;
    const int e0   = blockIdx.x * TILE_M;

    // indices / mask / biases (256 rows)
    if (tid < 256) {
        if (g_is64) {
            const long long* ei = (const long long*)edge_index;
            const long long* eg = (const long long*)eg_index;
            sS[tid] = (int)ei[e0 + tid];
            sR[tid] = (int)ei[E_TOTAL + e0 + tid];
            sG[tid] = (int)eg[e0 + tid];
        } else {
            const int* ei = (const int*)edge_index;
            const int* eg = (const int*)eg_index;
            sS[tid] = ei[e0 + tid];
            sR[tid] = ei[E_TOTAL + e0 + tid];
            sG[tid] = eg[e0 + tid];
        }
        sMsk[tid] = edge_mask[e0 + tid];
        if (tid < 128) sB1[tid] = b1[tid];
        if (tid < 64)  sB2[tid] = b2[tid];
    }

    // W2^T [64][64 h2] -> smem (2048 uint2 / 512 thr = 4 iters)
    #pragma unroll
    for (int i = 0; i < 4; i++) {
        int f = i * NTHREADS + tid, r = f >> 5, q = f & 31;
        uint2 u = *(const uint2*)(g_w2t2 + r * 64 + q * 2);
        *(uint2*)(sW22 + r * LDA + q * 2) = u;
    }

    // ---------------- GEMM1: H[256][128] = X[256][256] @ W1 -------------
    // 16 warps as 8(m) x 2(n); warp tile 32 x 64
    const int m0 = (w >> 1) * 32;
    const int n0 = (w & 1) * 64;
    float acc[2][8][4];
    #pragma unroll
    for (int mi = 0; mi < 2; mi++)
        #pragma unroll
        for (int ni = 0; ni < 8; ni++)
            #pragma unroll
            for (int j = 0; j < 4; j++) acc[mi][ni][j] = 0.0f;

    #pragma unroll 1
    for (int seg = 0; seg < 2; seg++) {
        __syncthreads();   // prev segment reads done (seg0: idx preload visible)

        // X half0 (h2 cols 0..31): seg0 = edge_attr (cvt), seg1 = receivers
        #pragma unroll
        for (int i = 0; i < 8; i++) {
            int f = i * NTHREADS + tid, r = f >> 4, q = f & 15;
            uint2 u;
            if (seg == 0) {
                float4 v = *(const float4*)(edge_attr + (size_t)(e0 + r) * 64 + q * 4);
                u.x = h2u(__floats2half2_rn(v.x, v.y));
                u.y = h2u(__floats2half2_rn(v.z, v.w));
            } else {
                u = *(const uint2*)(g_mn2 + (size_t)sR[r] * 32 + q * 2);
            }
            *(uint2*)(sX2 + r * LDA + q * 2) = u;
        }
        // X half1 (h2 cols 32..63): seg0 = senders, seg1 = globals
        #pragma unroll
        for (int i = 0; i < 8; i++) {
            int f = i * NTHREADS + tid, r = f >> 4, q = f & 15;
            uint2 u;
            if (seg == 0) u = *(const uint2*)(g_mn2 + (size_t)sS[r] * 32 + q * 2);
            else          u = *(const uint2*)(g_ga2 + (size_t)sG[r] * 32 + q * 2);
            *(uint2*)(sX2 + r * LDA + 32 + q * 2) = u;
        }
        // W1^T segment [128 n][64 h2]: 4096 uint2 / 512 thr = 8 iters
        #pragma unroll
        for (int i = 0; i < 8; i++) {
            int f = i * NTHREADS + tid, r = f >> 5, q = f & 31;
            uint2 u = *(const uint2*)(g_w1t2 + r * 128 + seg * 64 + q * 2);
            *(uint2*)(sW12 + r * LDA + q * 2) = u;
        }
        __syncthreads();

        // 8 k16-steps per segment
        #pragma unroll
        for (int k16 = 0; k16 < 8; k16++) {
            const int kk2 = k16 * 8;
            uint32_t a[2][4];
            #pragma unroll
            for (int mi = 0; mi < 2; mi++) {
                const uint32_t* A0 = (const uint32_t*)(sX2 + (m0 + mi * 16 + g) * LDA + kk2 + t);
                const uint32_t* A1 = (const uint32_t*)(sX2 + (m0 + mi * 16 + g + 8) * LDA + kk2 + t);
                a[mi][0] = A0[0]; a[mi][1] = A1[0];
                a[mi][2] = A0[4]; a[mi][3] = A1[4];
            }
            #pragma unroll
            for (int ni = 0; ni < 8; ni++) {
                const uint32_t* B = (const uint32_t*)(sW12 + (n0 + ni * 8 + g) * LDA + kk2 + t);
                uint32_t b[2] = { B[0], B[4] };
                mma_f16(acc[0][ni], a[0], b);
                mma_f16(acc[1][ni], a[1], b);
            }
        }
    }
    __syncthreads();   // all GEMM1 smem reads done before sH overwrite

    // ---- epilogue 1: bias + ReLU -> half2 -> sH (aliases sX) ----
    #pragma unroll
    for (int mi = 0; mi < 2; mi++) {
        #pragma unroll
        for (int ni = 0; ni < 8; ni++) {
            int row0 = m0 + mi * 16 + g;
            int row1 = row0 + 8;
            int col  = n0 + ni * 8 + 2 * t;
            float bb0 = sB1[col], bb1 = sB1[col + 1];
            float h00 = fmaxf(acc[mi][ni][0] + bb0, 0.0f);
            float h01 = fmaxf(acc[mi][ni][1] + bb1, 0.0f);
            float h10 = fmaxf(acc[mi][ni][2] + bb0, 0.0f);
            float h11 = fmaxf(acc[mi][ni][3] + bb1, 0.0f);
            sH2[row0 * LDA + (col >> 1)] = __floats2half2_rn(h00, h01);
            sH2[row1 * LDA + (col >> 1)] = __floats2half2_rn(h10, h11);
        }
    }
    __syncthreads();

    // ---------------- GEMM2: OUT[256][64] = H[256][128] @ W2 ------------
    // 16 warps as 8(m) x 2(n); warp tile 32 x 32
    const int m2 = (w >> 1) * 32;
    const int n2 = (w & 1) * 32;
    float acc2[2][4][4];
    #pragma unroll
    for (int mi = 0; mi < 2; mi++)
        #pragma unroll
        for (int ni = 0; ni < 4; ni++)
            #pragma unroll
            for (int j = 0; j < 4; j++) acc2[mi][ni][j] = 0.0f;

    #pragma unroll
    for (int k16 = 0; k16 < 8; k16++) {
        const int kk2 = k16 * 8;
        uint32_t a[2][4];
        #pragma unroll
        for (int mi = 0; mi < 2; mi++) {
            const uint32_t* A0 = (const uint32_t*)(sH2 + (m2 + mi * 16 + g) * LDA + kk2 + t);
            const uint32_t* A1 = (const uint32_t*)(sH2 + (m2 + mi * 16 + g + 8) * LDA + kk2 + t);
            a[mi][0] = A0[0]; a[mi][1] = A1[0];
            a[mi][2] = A0[4]; a[mi][3] = A1[4];
        }
        #pragma unroll
        for (int ni = 0; ni < 4; ni++) {
            const uint32_t* B = (const uint32_t*)(sW22 + (n2 + ni * 8 + g) * LDA + kk2 + t);
            uint32_t b[2] = { B[0], B[4] };
            mma_f16(acc2[0][ni], a[0], b);
            mma_f16(acc2[1][ni], a[1], b);
        }
    }

    // ---- epilogue 2: mask * (acc + b2), direct float2 stores ----
    #pragma unroll
    for (int mi = 0; mi < 2; mi++) {
        int row0 = m2 + mi * 16 + g;
        int row1 = row0 + 8;
        float mk0 = sMsk[row0];
        float mk1 = sMsk[row1];
        #pragma unroll
        for (int ni = 0; ni < 4; ni++) {
            int col = n2 + ni * 8 + 2 * t;
            float bb0 = sB2[col], bb1 = sB2[col + 1];
            float2 v0 = make_float2(mk0 * (acc2[mi][ni][0] + bb0),
                                    mk0 * (acc2[mi][ni][1] + bb1));
            float2 v1 = make_float2(mk1 * (acc2[mi][ni][2] + bb0),
                                    mk1 * (acc2[mi][ni][3] + bb1));
            *(float2*)(out + (size_t)(e0 + row0) * 64 + col) = v0;
            *(float2*)(out + (size_t)(e0 + row1) * 64 + col) = v1;
        }
    }
}

extern "C" void kernel_launch(void* const* d_in, const int* in_sizes, int n_in,
                              void* d_out, int out_size) {
    const float* node_attr   = (const float*)d_in[0];
    const float* edge_attr   = (const float*)d_in[1];
    const float* global_attr = (const float*)d_in[2];
    const float* node_mask   = (const float*)d_in[3];
    const float* edge_mask   = (const float*)d_in[4];
    const void*  edge_index  = d_in[5];
    const void*  eg_index    = d_in[6];
    const float* W1          = (const float*)d_in[7];
    const float* b1          = (const float*)d_in[8];
    const float* W2          = (const float*)d_in[9];
    const float* b2          = (const float*)d_in[10];
    float*       out         = (float*)d_out;

    cudaFuncSetAttribute(edge_mlp_kernel,
                         cudaFuncAttributeMaxDynamicSharedMemorySize, SMEM_BYTES);

    prep_all<<<PREP_BLOCKS, 256>>>(node_attr, node_mask, W1, W2, global_attr,
                                   (const int*)edge_index);
    edge_mlp_kernel<<<E_TOTAL / TILE_M, NTHREADS, SMEM_BYTES>>>(
        edge_attr, edge_mask, edge_index, eg_index, b1, b2, out);
}

// round 13
// speedup vs baseline: 1.0990x; 1.0990x over previous
#include <cuda_runtime.h>
#include <cuda_fp16.h>
#include <cstdint>

// Problem constants
#define E_TOTAL   640000
#define N_NODES   20000
#define N_GRAPHS  16
#define TILE_M    128
#define NTHREADS  256

#define LDA  68   // X/H [128][64 h2], padded (h2 units)

// smem byte offsets (X and H alias)
#define SMEM_X    0        // 128*68*4 = 34816
#define SMEM_H    0
#define OFF_S     34816
#define OFF_R     35328
#define OFF_G     35840
#define OFF_MSK   36352
#define OFF_B1    36864
#define OFF_B2    37376
#define SMEM_BYTES 37632

// ---------- scratch ----------
__device__ __half2 g_mn2[N_NODES * 32];    // masked nodes [node][32 h2]
__device__ __half2 g_ga2[N_GRAPHS * 32];   // global_attr fp16 [g][32 h2]
// fragment-linear weights: [s][n8][lane][2] h2  (uint2 per lane)
__device__ __half2 g_w1f[16 * 16 * 32 * 2];   // 16384 h2 = 64KB
__device__ __half2 g_w2f[8 * 8 * 32 * 2];     // 4096 h2 = 16KB
__device__ int     g_is64;

__device__ __forceinline__ void mma_f16(float c[4], const uint32_t a[4], const uint32_t b[2]) {
    asm volatile(
        "mma.sync.aligned.m16n8k16.row.col.f32.f16.f16.f32 "
        "{%0,%1,%2,%3}, {%4,%5,%6,%7}, {%8,%9}, {%0,%1,%2,%3};"
        : "+f"(c[0]), "+f"(c[1]), "+f"(c[2]), "+f"(c[3])
        : "r"(a[0]), "r"(a[1]), "r"(a[2]), "r"(a[3]), "r"(b[0]), "r"(b[1]));
}
__device__ __forceinline__ uint32_t h2u(__half2 h) { return *(uint32_t*)&h; }

// ---------- single prep kernel ----------
// blocks [0,2500): masked nodes; [2500,2564): W1 frag-linear; [2564,2580): W2
// frag-linear; [2580,2582): global_attr fp16; 2582: index dtype detect.
#define PREP_BLOCKS 2583
__global__ void prep_all(const float* __restrict__ na, const float* __restrict__ nm,
                         const float* __restrict__ W1, const float* __restrict__ W2,
                         const float* __restrict__ ga, const int* __restrict__ ei_words) {
    int bid = blockIdx.x, tid = threadIdx.x;
    if (bid < 2500) {
        int i = bid * 256 + tid;
        if (i < N_NODES * 32) {
            int node = i >> 5, c2 = i & 31;
            float m = nm[node];
            const float* s = na + (size_t)node * 64 + c2 * 2;
            g_mn2[i] = __floats2half2_rn(s[0] * m, s[1] * m);
        }
    } else if (bid < 2564) {
        // W1 [256][128] -> frag-linear: j = ((s*16+n8)*32+lane)*2+reg
        int j = (bid - 2500) * 256 + tid;       // < 16384
        int s   = j >> 10;
        int rem = j & 1023;
        int n8  = rem >> 6;
        int lane = (rem >> 1) & 31;
        int reg  = rem & 1;
        int g = lane >> 2, t = lane & 3;
        int n  = n8 * 8 + g;
        int k2 = s * 8 + t + reg * 4;
        g_w1f[j] = __floats2half2_rn(W1[(2 * k2) * 128 + n], W1[(2 * k2 + 1) * 128 + n]);
    } else if (bid < 2580) {
        // W2 [128][64] -> frag-linear
        int j = (bid - 2564) * 256 + tid;       // < 4096
        int s   = j >> 9;
        int rem = j & 511;
        int n8  = rem >> 6;
        int lane = (rem >> 1) & 31;
        int reg  = rem & 1;
        int g = lane >> 2, t = lane & 3;
        int n  = n8 * 8 + g;
        int k2 = s * 8 + t + reg * 4;
        g_w2f[j] = __floats2half2_rn(W2[(2 * k2) * 64 + n], W2[(2 * k2 + 1) * 64 + n]);
    } else if (bid < 2582) {
        int j = (bid - 2580) * 256 + tid;       // < 512
        if (j < N_GRAPHS * 32) {
            int gi = j >> 5, c2 = j & 31;
            g_ga2[j] = __floats2half2_rn(ga[gi * 64 + 2 * c2], ga[gi * 64 + 2 * c2 + 1]);
        }
    } else {
        __shared__ int nz;
        if (tid == 0) nz = 0;
        __syncthreads();
        int w = ei_words[2 * tid * 2500 + 1];
        if (w != 0) atomicAdd(&nz, 1);
        __syncthreads();
        if (tid == 0) g_is64 = (nz == 0) ? 1 : 0;
    }
}

// ---------- fused edge MLP: 128-edge tiles, 8 warps (4m x 2n), 2 CTAs/SM ----------
__global__ __launch_bounds__(NTHREADS, 2)
void edge_mlp_kernel(const float* __restrict__ edge_attr,
                     const float* __restrict__ edge_mask,
                     const void* __restrict__ edge_index,
                     const void* __restrict__ eg_index,
                     const float* __restrict__ b1,
                     const float* __restrict__ b2,
                     float* __restrict__ out) {
    extern __shared__ char smp[];
    __half2* sX2 = (__half2*)(smp + SMEM_X);
    __half2* sH2 = (__half2*)(smp + SMEM_H);
    int*   sS   = (int*)(smp + OFF_S);
    int*   sR   = (int*)(smp + OFF_R);
    int*   sG   = (int*)(smp + OFF_G);
    float* sMsk = (float*)(smp + OFF_MSK);
    float* sB1  = (float*)(smp + OFF_B1);
    float* sB2  = (float*)(smp + OFF_B2);

    const int tid  = threadIdx.x;
    const int lane = tid & 31;
    const int w    = tid >> 5;           // 0..7
    const int g    = lane >> 2;
    const int t    = lane & 3;
    const int e0   = blockIdx.x * TILE_M;

    const uint2* w1f = (const uint2*)g_w1f;   // [ (s*16+n8)*32 + lane ]
    const uint2* w2f = (const uint2*)g_w2f;   // [ (s*8 +n8)*32 + lane ]

    // indices / mask / biases
    if (tid < 128) {
        if (g_is64) {
            const long long* ei = (const long long*)edge_index;
            const long long* eg = (const long long*)eg_index;
            sS[tid] = (int)ei[e0 + tid];
            sR[tid] = (int)ei[E_TOTAL + e0 + tid];
            sG[tid] = (int)eg[e0 + tid];
        } else {
            const int* ei = (const int*)edge_index;
            const int* eg = (const int*)eg_index;
            sS[tid] = ei[e0 + tid];
            sR[tid] = ei[E_TOTAL + e0 + tid];
            sG[tid] = eg[e0 + tid];
        }
        sMsk[tid] = edge_mask[e0 + tid];
        sB1[tid]  = b1[tid];
        if (tid < 64) sB2[tid] = b2[tid];
    }

    // ---------------- GEMM1: H[128][128] = X[128][256] @ W1 -------------
    // 8 warps as 4(m) x 2(n); warp tile 32 x 64
    const int m0 = (w >> 1) * 32;
    const int wn = w & 1;                // n-column: n0 = wn*64
    float acc[2][8][4];
    #pragma unroll
    for (int mi = 0; mi < 2; mi++)
        #pragma unroll
        for (int ni = 0; ni < 8; ni++)
            #pragma unroll
            for (int j = 0; j < 4; j++) acc[mi][ni][j] = 0.0f;

    #pragma unroll 1
    for (int seg = 0; seg < 2; seg++) {
        __syncthreads();   // prev segment reads done (seg0: idx preload visible)

        // X half0 (h2 cols 0..31): seg0 = edge_attr (cvt), seg1 = receivers
        #pragma unroll
        for (int i = 0; i < 8; i++) {
            int f = i * NTHREADS + tid, r = f >> 4, q = f & 15;
            uint2 u;
            if (seg == 0) {
                float4 v = *(const float4*)(edge_attr + (size_t)(e0 + r) * 64 + q * 4);
                u.x = h2u(__floats2half2_rn(v.x, v.y));
                u.y = h2u(__floats2half2_rn(v.z, v.w));
            } else {
                u = *(const uint2*)(g_mn2 + (size_t)sR[r] * 32 + q * 2);
            }
            *(uint2*)(sX2 + r * LDA + q * 2) = u;
        }
        // X half1 (h2 cols 32..63): seg0 = senders, seg1 = globals
        #pragma unroll
        for (int i = 0; i < 8; i++) {
            int f = i * NTHREADS + tid, r = f >> 4, q = f & 15;
            uint2 u;
            if (seg == 0) u = *(const uint2*)(g_mn2 + (size_t)sS[r] * 32 + q * 2);
            else          u = *(const uint2*)(g_ga2 + (size_t)sG[r] * 32 + q * 2);
            *(uint2*)(sX2 + r * LDA + 32 + q * 2) = u;
        }
        __syncthreads();

        // 8 k16-steps per segment; B fragments straight from L1-resident gmem
        #pragma unroll
        for (int k16 = 0; k16 < 8; k16++) {
            const int s   = seg * 8 + k16;
            const int kk2 = k16 * 8;
            uint32_t a[2][4];
            #pragma unroll
            for (int mi = 0; mi < 2; mi++) {
                const uint32_t* A0 = (const uint32_t*)(sX2 + (m0 + mi * 16 + g) * LDA + kk2 + t);
                const uint32_t* A1 = (const uint32_t*)(sX2 + (m0 + mi * 16 + g + 8) * LDA + kk2 + t);
                a[mi][0] = A0[0]; a[mi][1] = A1[0];
                a[mi][2] = A0[4]; a[mi][3] = A1[4];
            }
            #pragma unroll
            for (int ni = 0; ni < 8; ni++) {
                int n8 = wn * 8 + ni;
                uint2 bu = w1f[(s * 16 + n8) * 32 + lane];
                uint32_t b[2] = { bu.x, bu.y };
                mma_f16(acc[0][ni], a[0], b);
                mma_f16(acc[1][ni], a[1], b);
            }
        }
    }
    __syncthreads();   // all GEMM1 smem reads done before sH overwrite

    // ---- epilogue 1: bias + ReLU -> half2 -> sH (aliases sX) ----
    #pragma unroll
    for (int mi = 0; mi < 2; mi++) {
        #pragma unroll
        for (int ni = 0; ni < 8; ni++) {
            int row0 = m0 + mi * 16 + g;
            int row1 = row0 + 8;
            int col  = wn * 64 + ni * 8 + 2 * t;
            float bb0 = sB1[col], bb1 = sB1[col + 1];
            float h00 = fmaxf(acc[mi][ni][0] + bb0, 0.0f);
            float h01 = fmaxf(acc[mi][ni][1] + bb1, 0.0f);
            float h10 = fmaxf(acc[mi][ni][2] + bb0, 0.0f);
            float h11 = fmaxf(acc[mi][ni][3] + bb1, 0.0f);
            sH2[row0 * LDA + (col >> 1)] = __floats2half2_rn(h00, h01);
            sH2[row1 * LDA + (col >> 1)] = __floats2half2_rn(h10, h11);
        }
    }
    __syncthreads();

    // ---------------- GEMM2: OUT[128][64] = H[128][128] @ W2 ------------
    // 8 warps as 4(m) x 2(n); warp tile 32 x 32
    const int m2 = m0;
    float acc2[2][4][4];
    #pragma unroll
    for (int mi = 0; mi < 2; mi++)
        #pragma unroll
        for (int ni = 0; ni < 4; ni++)
            #pragma unroll
            for (int j = 0; j < 4; j++) acc2[mi][ni][j] = 0.0f;

    #pragma unroll
    for (int s = 0; s < 8; s++) {
        const int kk2 = s * 8;
        uint32_t a[2][4];
        #pragma unroll
        for (int mi = 0; mi < 2; mi++) {
            const uint32_t* A0 = (const uint32_t*)(sH2 + (m2 + mi * 16 + g) * LDA + kk2 + t);
            const uint32_t* A1 = (const uint32_t*)(sH2 + (m2 + mi * 16 + g + 8) * LDA + kk2 + t);
            a[mi][0] = A0[0]; a[mi][1] = A1[0];
            a[mi][2] = A0[4]; a[mi][3] = A1[4];
        }
        #pragma unroll
        for (int ni = 0; ni < 4; ni++) {
            int n8 = wn * 4 + ni;
            uint2 bu = w2f[(s * 8 + n8) * 32 + lane];
            uint32_t b[2] = { bu.x, bu.y };
            mma_f16(acc2[0][ni], a[0], b);
            mma_f16(acc2[1][ni], a[1], b);
        }
    }

    // ---- epilogue 2: mask * (acc + b2), direct float2 stores ----
    #pragma unroll
    for (int mi = 0; mi < 2; mi++) {
        int row0 = m2 + mi * 16 + g;
        int row1 = row0 + 8;
        float mk0 = sMsk[row0];
        float mk1 = sMsk[row1];
        #pragma unroll
        for (int ni = 0; ni < 4; ni++) {
            int col = wn * 32 + ni * 8 + 2 * t;
            float bb0 = sB2[col], bb1 = sB2[col + 1];
            float2 v0 = make_float2(mk0 * (acc2[mi][ni][0] + bb0),
                                    mk0 * (acc2[mi][ni][1] + bb1));
            float2 v1 = make_float2(mk1 * (acc2[mi][ni][2] + bb0),
                                    mk1 * (acc2[mi][ni][3] + bb1));
            *(float2*)(out + (size_t)(e0 + row0) * 64 + col) = v0;
            *(float2*)(out + (size_t)(e0 + row1) * 64 + col) = v1;
        }
    }
}

extern "C" void kernel_launch(void* const* d_in, const int* in_sizes, int n_in,
                              void* d_out, int out_size) {
    const float* node_attr   = (const float*)d_in[0];
    const float* edge_attr   = (const float*)d_in[1];
    const float* global_attr = (const float*)d_in[2];
    const float* node_mask   = (const float*)d_in[3];
    const float* edge_mask   = (const float*)d_in[4];
    const void*  edge_index  = d_in[5];
    const void*  eg_index    = d_in[6];
    const float* W1          = (const float*)d_in[7];
    const float* b1          = (const float*)d_in[8];
    const float* W2          = (const float*)d_in[9];
    const float* b2          = (const float*)d_in[10];
    float*       out         = (float*)d_out;

    cudaFuncSetAttribute(edge_mlp_kernel,
                         cudaFuncAttributeMaxDynamicSharedMemorySize, SMEM_BYTES);

    prep_all<<<PREP_BLOCKS, 256>>>(node_attr, node_mask, W1, W2, global_attr,
                                   (const int*)edge_index);
    edge_mlp_kernel<<<E_TOTAL / TILE_M, NTHREADS, SMEM_BYTES>>>(
        edge_attr, edge_mask, edge_index, eg_index, b1, b2, out);
}

// round 14
// speedup vs baseline: 1.4352x; 1.3059x over previous
#include <cuda_runtime.h>
#include <cuda_fp16.h>
#include <cstdint>

// Problem constants
#define E_TOTAL   640000
#define N_NODES   20000
#define N_GRAPHS  16
#define TILE_M    128
#define NTHREADS  512

#define LDA  68   // X buf / H rows [128][64 h2], padded (h2 units)

// smem byte offsets: two X buffers; H aliases buf0
#define SMEM_X0   0        // 128*68*4 = 34816
#define SMEM_X1   34816    // -> 69632
#define SMEM_H    0
#define OFF_S     69632
#define OFF_R     70144
#define OFF_G     70656
#define OFF_MSK   71168
#define OFF_B1    71680
#define OFF_B2    72192
#define SMEM_BYTES 72448

// ---------- scratch ----------
__device__ __half2 g_mn2[N_NODES * 32];    // masked nodes [node][32 h2]
__device__ __half2 g_ga2[N_GRAPHS * 32];   // global_attr fp16 [g][32 h2]
// fragment-linear weights: [s][n8][lane][2] h2 (one uint2 per lane)
__device__ __half2 g_w1f[16 * 16 * 32 * 2];   // 64KB
__device__ __half2 g_w2f[8 * 8 * 32 * 2];     // 16KB
__device__ int     g_is64;

__device__ __forceinline__ void mma_f16(float c[4], const uint32_t a[4], const uint32_t b[2]) {
    asm volatile(
        "mma.sync.aligned.m16n8k16.row.col.f32.f16.f16.f32 "
        "{%0,%1,%2,%3}, {%4,%5,%6,%7}, {%8,%9}, {%0,%1,%2,%3};"
        : "+f"(c[0]), "+f"(c[1]), "+f"(c[2]), "+f"(c[3])
        : "r"(a[0]), "r"(a[1]), "r"(a[2]), "r"(a[3]), "r"(b[0]), "r"(b[1]));
}
__device__ __forceinline__ uint32_t h2u(__half2 h) { return *(uint32_t*)&h; }

// ---------- single prep kernel ----------
// blocks [0,2500): masked nodes; [2500,2564): W1 frag-linear; [2564,2580): W2
// frag-linear; [2580,2582): global_attr fp16; 2582: index dtype detect.
#define PREP_BLOCKS 2583
__global__ void prep_all(const float* __restrict__ na, const float* __restrict__ nm,
                         const float* __restrict__ W1, const float* __restrict__ W2,
                         const float* __restrict__ ga, const int* __restrict__ ei_words) {
    int bid = blockIdx.x, tid = threadIdx.x;
    if (bid < 2500) {
        int i = bid * 256 + tid;
        if (i < N_NODES * 32) {
            int node = i >> 5, c2 = i & 31;
            float m = nm[node];
            const float* s = na + (size_t)node * 64 + c2 * 2;
            g_mn2[i] = __floats2half2_rn(s[0] * m, s[1] * m);
        }
    } else if (bid < 2564) {
        // W1 [256][128] -> frag-linear: j = ((s*16+n8)*32+lane)*2+reg
        int j = (bid - 2500) * 256 + tid;       // < 16384
        int s   = j >> 10;
        int rem = j & 1023;
        int n8  = rem >> 6;
        int lane = (rem >> 1) & 31;
        int reg  = rem & 1;
        int g = lane >> 2, t = lane & 3;
        int n  = n8 * 8 + g;
        int k2 = s * 8 + t + reg * 4;
        g_w1f[j] = __floats2half2_rn(W1[(2 * k2) * 128 + n], W1[(2 * k2 + 1) * 128 + n]);
    } else if (bid < 2580) {
        // W2 [128][64] -> frag-linear
        int j = (bid - 2564) * 256 + tid;       // < 4096
        int s   = j >> 9;
        int rem = j & 511;
        int n8  = rem >> 6;
        int lane = (rem >> 1) & 31;
        int reg  = rem & 1;
        int g = lane >> 2, t = lane & 3;
        int n  = n8 * 8 + g;
        int k2 = s * 8 + t + reg * 4;
        g_w2f[j] = __floats2half2_rn(W2[(2 * k2) * 64 + n], W2[(2 * k2 + 1) * 64 + n]);
    } else if (bid < 2582) {
        int j = (bid - 2580) * 256 + tid;       // < 512
        if (j < N_GRAPHS * 32) {
            int gi = j >> 5, c2 = j & 31;
            g_ga2[j] = __floats2half2_rn(ga[gi * 64 + 2 * c2], ga[gi * 64 + 2 * c2 + 1]);
        }
    } else {
        __shared__ int nz;
        if (tid == 0) nz = 0;
        __syncthreads();
        int w = ei_words[2 * tid * 2500 + 1];
        if (w != 0) atomicAdd(&nz, 1);
        __syncthreads();
        if (tid == 0) g_is64 = (nz == 0) ? 1 : 0;
    }
}

// ---------- fused edge MLP: 512 thr, 4m x 4n, double-buffered X, gmem B frags ----------
__global__ __launch_bounds__(NTHREADS, 2)
void edge_mlp_kernel(const float* __restrict__ edge_attr,
                     const float* __restrict__ edge_mask,
                     const void* __restrict__ edge_index,
                     const void* __restrict__ eg_index,
                     const float* __restrict__ b1,
                     const float* __restrict__ b2,
                     float* __restrict__ out) {
    extern __shared__ char smp[];
    __half2* sX[2] = { (__half2*)(smp + SMEM_X0), (__half2*)(smp + SMEM_X1) };
    __half2* sH2 = (__half2*)(smp + SMEM_H);
    int*   sS   = (int*)(smp + OFF_S);
    int*   sR   = (int*)(smp + OFF_R);
    int*   sG   = (int*)(smp + OFF_G);
    float* sMsk = (float*)(smp + OFF_MSK);
    float* sB1  = (float*)(smp + OFF_B1);
    float* sB2  = (float*)(smp + OFF_B2);

    const int tid  = threadIdx.x;
    const int lane = tid & 31;
    const int w    = tid >> 5;           // 0..15
    const int g    = lane >> 2;
    const int t    = lane & 3;
    const int e0   = blockIdx.x * TILE_M;

    const uint2* w1f = (const uint2*)g_w1f;   // [ (s*16+n8)*32 + lane ]
    const uint2* w2f = (const uint2*)g_w2f;   // [ (s*8 +n8)*32 + lane ]

    // indices / mask / biases
    if (tid < 128) {
        if (g_is64) {
            const long long* ei = (const long long*)edge_index;
            const long long* eg = (const long long*)eg_index;
            sS[tid] = (int)ei[e0 + tid];
            sR[tid] = (int)ei[E_TOTAL + e0 + tid];
            sG[tid] = (int)eg[e0 + tid];
        } else {
            const int* ei = (const int*)edge_index;
            const int* eg = (const int*)eg_index;
            sS[tid] = ei[e0 + tid];
            sR[tid] = ei[E_TOTAL + e0 + tid];
            sG[tid] = eg[e0 + tid];
        }
        sMsk[tid] = edge_mask[e0 + tid];
        sB1[tid]  = b1[tid];
        if (tid < 64) sB2[tid] = b2[tid];
    }
    __syncthreads();

    // ---- stage helper (inlined twice): fills sX[buf] with segment seg ----
    // seg0: half0 = edge_attr (cvt f32->f16), half1 = senders
    // seg1: half0 = receivers,               half1 = globals
    #define STAGE_X(SEG, BUF) do {                                              \
        _Pragma("unroll")                                                       \
        for (int i = 0; i < 4; i++) {                                           \
            int f = i * NTHREADS + tid, r = f >> 4, q = f & 15;                 \
            uint2 u;                                                            \
            if ((SEG) == 0) {                                                   \
                float4 v = *(const float4*)(edge_attr + (size_t)(e0 + r) * 64 + q * 4); \
                u.x = h2u(__floats2half2_rn(v.x, v.y));                         \
                u.y = h2u(__floats2half2_rn(v.z, v.w));                         \
            } else {                                                            \
                u = *(const uint2*)(g_mn2 + (size_t)sR[r] * 32 + q * 2);        \
            }                                                                   \
            *(uint2*)(sX[BUF] + r * LDA + q * 2) = u;                           \
        }                                                                       \
        _Pragma("unroll")                                                       \
        for (int i = 0; i < 4; i++) {                                           \
            int f = i * NTHREADS + tid, r = f >> 4, q = f & 15;                 \
            uint2 u;                                                            \
            if ((SEG) == 0) u = *(const uint2*)(g_mn2 + (size_t)sS[r] * 32 + q * 2); \
            else            u = *(const uint2*)(g_ga2 + (size_t)sG[r] * 32 + q * 2); \
            *(uint2*)(sX[BUF] + r * LDA + 32 + q * 2) = u;                      \
        }                                                                       \
    } while (0)

    // ---------------- GEMM1: H[128][128] = X[128][256] @ W1 -------------
    // 16 warps as 4(m) x 4(n); warp tile 32 x 32
    const int m0 = (w & 3) * 32;
    const int wn = w >> 2;               // 0..3, n-block of 32
    float acc[2][4][4];
    #pragma unroll
    for (int mi = 0; mi < 2; mi++)
        #pragma unroll
        for (int ni = 0; ni < 4; ni++)
            #pragma unroll
            for (int j = 0; j < 4; j++) acc[mi][ni][j] = 0.0f;

    STAGE_X(0, 0);
    __syncthreads();
    STAGE_X(1, 1);          // overlaps with seg0 compute below (per-warp scoreboard)

    #pragma unroll
    for (int seg = 0; seg < 2; seg++) {
        const __half2* sXb = sX[seg];
        #pragma unroll
        for (int k16 = 0; k16 < 8; k16++) {
            const int s   = seg * 8 + k16;
            const int kk2 = k16 * 8;
            uint32_t a[2][4];
            #pragma unroll
            for (int mi = 0; mi < 2; mi++) {
                const uint32_t* A0 = (const uint32_t*)(sXb + (m0 + mi * 16 + g) * LDA + kk2 + t);
                const uint32_t* A1 = (const uint32_t*)(sXb + (m0 + mi * 16 + g + 8) * LDA + kk2 + t);
                a[mi][0] = A0[0]; a[mi][1] = A1[0];
                a[mi][2] = A0[4]; a[mi][3] = A1[4];
            }
            #pragma unroll
            for (int ni = 0; ni < 4; ni++) {
                int n8 = wn * 4 + ni;
                uint2 bu = w1f[(s * 16 + n8) * 32 + lane];
                uint32_t b[2] = { bu.x, bu.y };
                mma_f16(acc[0][ni], a[0], b);
                mma_f16(acc[1][ni], a[1], b);
            }
        }
        if (seg == 0) __syncthreads();   // buf1 fully staged before seg1 reads
    }
    __syncthreads();   // all buf reads done before H (aliases buf0) overwrite

    // ---- epilogue 1: bias + ReLU -> half2 -> sH ----
    #pragma unroll
    for (int mi = 0; mi < 2; mi++) {
        #pragma unroll
        for (int ni = 0; ni < 4; ni++) {
            int row0 = m0 + mi * 16 + g;
            int row1 = row0 + 8;
            int col  = wn * 32 + ni * 8 + 2 * t;
            float bb0 = sB1[col], bb1 = sB1[col + 1];
            float h00 = fmaxf(acc[mi][ni][0] + bb0, 0.0f);
            float h01 = fmaxf(acc[mi][ni][1] + bb1, 0.0f);
            float h10 = fmaxf(acc[mi][ni][2] + bb0, 0.0f);
            float h11 = fmaxf(acc[mi][ni][3] + bb1, 0.0f);
            sH2[row0 * LDA + (col >> 1)] = __floats2half2_rn(h00, h01);
            sH2[row1 * LDA + (col >> 1)] = __floats2half2_rn(h10, h11);
        }
    }
    __syncthreads();

    // ---------------- GEMM2: OUT[128][64] = H[128][128] @ W2 ------------
    // 16 warps as 4(m) x 4(n); warp tile 32 x 16
    const int m2 = m0;
    const int n2 = wn * 16;
    float acc2[2][2][4];
    #pragma unroll
    for (int mi = 0; mi < 2; mi++)
        #pragma unroll
        for (int ni = 0; ni < 2; ni++)
            #pragma unroll
            for (int j = 0; j < 4; j++) acc2[mi][ni][j] = 0.0f;

    #pragma unroll
    for (int s = 0; s < 8; s++) {
        const int kk2 = s * 8;
        uint32_t a[2][4];
        #pragma unroll
        for (int mi = 0; mi < 2; mi++) {
            const uint32_t* A0 = (const uint32_t*)(sH2 + (m2 + mi * 16 + g) * LDA + kk2 + t);
            const uint32_t* A1 = (const uint32_t*)(sH2 + (m2 + mi * 16 + g + 8) * LDA + kk2 + t);
            a[mi][0] = A0[0]; a[mi][1] = A1[0];
            a[mi][2] = A0[4]; a[mi][3] = A1[4];
        }
        #pragma unroll
        for (int ni = 0; ni < 2; ni++) {
            int n8 = wn * 2 + ni;
            uint2 bu = w2f[(s * 8 + n8) * 32 + lane];
            uint32_t b[2] = { bu.x, bu.y };
            mma_f16(acc2[0][ni], a[0], b);
            mma_f16(acc2[1][ni], a[1], b);
        }
    }

    // ---- epilogue 2: mask * (acc + b2), direct float2 stores ----
    #pragma unroll
    for (int mi = 0; mi < 2; mi++) {
        int row0 = m2 + mi * 16 + g;
        int row1 = row0 + 8;
        float mk0 = sMsk[row0];
        float mk1 = sMsk[row1];
        #pragma unroll
        for (int ni = 0; ni < 2; ni++) {
            int col = n2 + ni * 8 + 2 * t;
            float bb0 = sB2[col], bb1 = sB2[col + 1];
            float2 v0 = make_float2(mk0 * (acc2[mi][ni][0] + bb0),
                                    mk0 * (acc2[mi][ni][1] + bb1));
            float2 v1 = make_float2(mk1 * (acc2[mi][ni][2] + bb0),
                                    mk1 * (acc2[mi][ni][3] + bb1));
            *(float2*)(out + (size_t)(e0 + row0) * 64 + col) = v0;
            *(float2*)(out + (size_t)(e0 + row1) * 64 + col) = v1;
        }
    }
    #undef STAGE_X
}

extern "C" void kernel_launch(void* const* d_in, const int* in_sizes, int n_in,
                              void* d_out, int out_size) {
    const float* node_attr   = (const float*)d_in[0];
    const float* edge_attr   = (const float*)d_in[1];
    const float* global_attr = (const float*)d_in[2];
    const float* node_mask   = (const float*)d_in[3];
    const float* edge_mask   = (const float*)d_in[4];
    const void*  edge_index  = d_in[5];
    const void*  eg_index    = d_in[6];
    const float* W1          = (const float*)d_in[7];
    const float* b1          = (const float*)d_in[8];
    const float* W2          = (const float*)d_in[9];
    const float* b2          = (const float*)d_in[10];
    float*       out         = (float*)d_out;

    cudaFuncSetAttribute(edge_mlp_kernel,
                         cudaFuncAttributeMaxDynamicSharedMemorySize, SMEM_BYTES);

    prep_all<<<PREP_BLOCKS, 256>>>(node_attr, node_mask, W1, W2, global_attr,
                                   (const int*)edge_index);
    edge_mlp_kernel<<<E_TOTAL / TILE_M, NTHREADS, SMEM_BYTES>>>(
        edge_attr, edge_mask, edge_index, eg_index, b1, b2, out);
}